// round 3
// baseline (speedup 1.0000x reference)
#include <cuda_runtime.h>
#include <float.h>
#include <math.h>

#define NB 16
#define NP 1024
#define NC 91
#define MAX_DET 100
#define SCORE_THRESH 0.05f
#define NMS_THRESH 0.5f
#define BBOX_CLIP 4.135166556742356f  /* log(1000/16) */

#define NMS_WARPS_PER_CTA 4
#define BOX_CACHE 240   /* per-warp smem box cache capacity */

// ---------------- scratch (no allocations allowed) ----------------
__device__ float  g_scores[NB * NP];
__device__ int    g_labels[NB * NP];
__device__ float4 g_boxes[NB * NP];
__device__ int    g_valid[NB * NP];
__device__ int    g_kept[NB * NP];
__device__ float  g_K[NB];

// ---------------- Kernel A: softmax-max/argmax + decode + clip ----------------
// One warp per proposal. Lanes cover classes {lane, lane+32, lane+64}.
__global__ void score_decode_kernel(const float* __restrict__ logits,
                                    const float* __restrict__ deltas,
                                    const float* __restrict__ props,
                                    const int*   __restrict__ imsz) {
    int gw   = (blockIdx.x * blockDim.x + threadIdx.x) >> 5;
    int lane = threadIdx.x & 31;
    if (gw >= NB * NP) return;

    const float* row = logits + (size_t)gw * NC;
    float l0 = row[lane];
    float l1 = row[lane + 32];
    bool  has2 = (lane < NC - 64);           // lane < 27
    float l2 = has2 ? row[lane + 64] : -FLT_MAX;

    // local argmax with first-index tie break
    float bv = l0; int bi = lane;
    if (l1 > bv) { bv = l1; bi = lane + 32; }
    if (l2 > bv) { bv = l2; bi = lane + 64; }
    #pragma unroll
    for (int o = 16; o; o >>= 1) {
        float ov = __shfl_down_sync(0xffffffffu, bv, o);
        int   oi = __shfl_down_sync(0xffffffffu, bi, o);
        if (ov > bv || (ov == bv && oi < bi)) { bv = ov; bi = oi; }
    }
    bv = __shfl_sync(0xffffffffu, bv, 0);
    bi = __shfl_sync(0xffffffffu, bi, 0);

    float s = expf(l0 - bv) + expf(l1 - bv) + (has2 ? expf(l2 - bv) : 0.0f);
    #pragma unroll
    for (int o = 16; o; o >>= 1) s += __shfl_down_sync(0xffffffffu, s, o);

    if (lane == 0) {
        float score = 1.0f / s;
        int label = bi;
        int b = gw / NP;
        int valid = (label > 0) && (score > SCORE_THRESH);

        const float* p = props + (size_t)gw * 4;
        float x1 = p[0], y1 = p[1], x2 = p[2], y2 = p[3];
        float w = x2 - x1, h = y2 - y1;
        float cx = x1 + 0.5f * w, cy = y1 + 0.5f * h;

        const float* dd = deltas + (size_t)gw * (NC * 4) + 4 * label;
        float dx = dd[0], dy = dd[1];
        float dw = fminf(dd[2], BBOX_CLIP), dh = fminf(dd[3], BBOX_CLIP);
        float pcx = dx * w + cx, pcy = dy * h + cy;
        float pw = expf(dw) * w, ph = expf(dh) * h;
        float bx1 = pcx - 0.5f * pw, by1 = pcy - 0.5f * ph;
        float bx2 = pcx + 0.5f * pw, by2 = pcy + 0.5f * ph;

        float hb = (float)imsz[b * 2 + 0];
        float wb = (float)imsz[b * 2 + 1];
        bx1 = fminf(fmaxf(bx1, 0.0f), wb);
        by1 = fminf(fmaxf(by1, 0.0f), hb);
        bx2 = fminf(fmaxf(bx2, 0.0f), wb);
        by2 = fminf(fmaxf(by2, 0.0f), hb);

        g_boxes[gw]  = make_float4(bx1, by1, bx2, by2);
        g_scores[gw] = score;
        g_labels[gw] = label;
        g_valid[gw]  = valid;
        g_kept[gw]   = 0;
    }
}

// ---------------- Kernel A2: per-image max_coord (+1) ----------------
// One warp per image; 1 CTA of 512 threads.
__global__ void maxcoord_kernel() {
    int warp = threadIdx.x >> 5;
    int lane = threadIdx.x & 31;
    if (warp >= NB) return;
    int base = warp * NP;
    float mc = 0.0f;
    #pragma unroll 4
    for (int i = lane; i < NP; i += 32) {
        if (g_valid[base + i]) {
            float4 v = g_boxes[base + i];
            mc = fmaxf(mc, fmaxf(fmaxf(v.x, v.y), fmaxf(v.z, v.w)));
        }
    }
    #pragma unroll
    for (int o = 16; o; o >>= 1)
        mc = fmaxf(mc, __shfl_xor_sync(0xffffffffu, mc, o));
    if (lane == 0) g_K[warp] = mc + 1.0f;
}

// ---------------- Kernel B: NMS, one warp per (image, class) ----------------
__global__ __launch_bounds__(NMS_WARPS_PER_CTA * 32)
void nms_class_kernel() {
    __shared__ unsigned long long s_key[NMS_WARPS_PER_CTA][NP];      // 32 KB
    __shared__ float4             s_box[NMS_WARPS_PER_CTA][BOX_CACHE]; // 15 KB

    int wslot = threadIdx.x >> 5;
    int lane  = threadIdx.x & 31;
    int W = blockIdx.x * NMS_WARPS_PER_CTA + wslot;
    if (W >= NB * 90) return;
    int b = W / 90;
    int c = 1 + (W % 90);
    int base = b * NP;

    float K = g_K[b];
    float off = (float)c * K;   // label * (max_coord + 1), same FP op order as reference

    // --- compact entries of class c into per-warp list (sorted-by-index order) ---
    int cnt = 0;
    for (int i = lane; i < NP; i += 32) {
        bool m = g_valid[base + i] && (g_labels[base + i] == c);
        unsigned bal = __ballot_sync(0xffffffffu, m);
        int pos = cnt + __popc(bal & ((1u << lane) - 1u));
        if (m) {
            unsigned int ds = ~__float_as_uint(g_scores[base + i]);
            s_key[wslot][pos] = ((unsigned long long)ds << 20) |
                                ((unsigned long long)(unsigned)i << 10) |
                                (unsigned long long)(unsigned)pos;
            if (pos < BOX_CACHE) {
                float4 v = g_boxes[base + i];
                s_box[wslot][pos] = make_float4(v.x + off, v.y + off,
                                                v.z + off, v.w + off);
            }
        }
        cnt += __popc(bal);
    }
    __syncwarp();

    // --- alive bitmask: lane owns positions {lane, lane+32, ...}, bit j = pos j*32+lane ---
    unsigned alive = 0;
    for (int j = 0; j * 32 + lane < cnt && j < 32; ++j) alive |= (1u << j);

    // --- greedy NMS: iteratively select max-score survivor, suppress overlaps ---
    while (true) {
        unsigned long long best = ~0ULL;
        unsigned am = alive;
        while (am) {
            int j = __ffs(am) - 1; am &= am - 1;
            unsigned long long k = s_key[wslot][j * 32 + lane];
            if (k < best) best = k;
        }
        #pragma unroll
        for (int o = 16; o; o >>= 1) {
            unsigned long long ob = __shfl_xor_sync(0xffffffffu, best, o);
            if (ob < best) best = ob;
        }
        if (best == ~0ULL) break;

        int pos_b = (int)(best & 1023ULL);
        int i0_b  = (int)((best >> 10) & 1023ULL);
        if ((pos_b & 31) == lane) {
            alive &= ~(1u << (pos_b >> 5));
            g_kept[base + i0_b] = 1;
        }

        float4 A;
        if (pos_b < BOX_CACHE) {
            A = s_box[wslot][pos_b];
        } else {
            float4 v = g_boxes[base + i0_b];
            A = make_float4(v.x + off, v.y + off, v.z + off, v.w + off);
        }
        float areaA = (A.z - A.x) * (A.w - A.y);

        am = alive;
        while (am) {
            int j = __ffs(am) - 1; am &= am - 1;
            int e = j * 32 + lane;
            float4 Bx;
            if (e < BOX_CACHE) {
                Bx = s_box[wslot][e];
            } else {
                int i0 = (int)((s_key[wslot][e] >> 10) & 1023ULL);
                float4 v = g_boxes[base + i0];
                Bx = make_float4(v.x + off, v.y + off, v.z + off, v.w + off);
            }
            float areaB = (Bx.z - Bx.x) * (Bx.w - Bx.y);
            float ltx = fmaxf(A.x, Bx.x), lty = fmaxf(A.y, Bx.y);
            float rbx = fminf(A.z, Bx.z), rby = fminf(A.w, Bx.w);
            float wx = fmaxf(rbx - ltx, 0.0f), wy = fmaxf(rby - lty, 0.0f);
            float inter = wx * wy;
            float iou = inter / (areaA + areaB - inter + 1e-9f);
            if (iou > NMS_THRESH) alive &= ~(1u << j);
        }
        __syncwarp();
    }
}

// ---------------- hybrid bitonic helpers ----------------
__device__ __forceinline__ unsigned long long cswap_shfl(unsigned long long key,
                                                         int t, int j, int k) {
    unsigned long long other = __shfl_xor_sync(0xffffffffu, key, j);
    bool up      = ((t & k) == 0);
    bool lower   = ((t & j) == 0);
    bool keepmin = (lower == up);
    unsigned long long mn = key < other ? key : other;
    unsigned long long mx = key < other ? other : key;
    return keepmin ? mn : mx;
}

__device__ __forceinline__ void bitonic_sort_1024(unsigned long long* s_key, int t) {
    unsigned long long key = s_key[t];
    #pragma unroll
    for (int k = 2; k <= 32; k <<= 1) {
        #pragma unroll
        for (int j = k >> 1; j >= 1; j >>= 1) key = cswap_shfl(key, t, j, k);
    }
    s_key[t] = key;
    __syncthreads();

    for (int k = 64; k <= 1024; k <<= 1) {
        for (int j = k >> 1; j >= 32; j >>= 1) {
            if ((t & j) == 0) {
                unsigned long long a = s_key[t];
                unsigned long long c = s_key[t ^ j];
                bool up = ((t & k) == 0);
                if ((a > c) == up) { s_key[t] = c; s_key[t ^ j] = a; }
            }
            __syncthreads();
        }
        key = s_key[t];
        #pragma unroll
        for (int j = 16; j >= 1; j >>= 1) key = cswap_shfl(key, t, j, k);
        s_key[t] = key;
        __syncthreads();
    }
}

// ---------------- Kernel C: per-image top-100 by score among kept ----------------
__global__ __launch_bounds__(1024) void topk_kernel(float* __restrict__ out) {
    const int b = blockIdx.x;
    const int t = threadIdx.x;
    __shared__ unsigned long long s_key[NP];

    const int g = b * NP + t;
    unsigned long long k = ~0ULL;
    if (g_kept[g]) {
        unsigned int ds = ~__float_as_uint(g_scores[g]);
        k = ((unsigned long long)ds << 10) | (unsigned long long)(unsigned)t;
    }
    s_key[t] = k;
    __syncthreads();

    bitonic_sort_1024(s_key, t);

    if (t < MAX_DET) {
        float* boxes_out  = out;
        float* scores_out = out + NB * MAX_DET * 4;
        float* labels_out = out + NB * MAX_DET * 5;
        unsigned long long kt = s_key[t];
        int base = b * MAX_DET + t;
        if (kt != ~0ULL) {
            int oi = (int)(kt & 1023ULL);
            float4 v = g_boxes[b * NP + oi];
            boxes_out[base * 4 + 0] = v.x;
            boxes_out[base * 4 + 1] = v.y;
            boxes_out[base * 4 + 2] = v.z;
            boxes_out[base * 4 + 3] = v.w;
            scores_out[base] = g_scores[b * NP + oi];
            labels_out[base] = (float)g_labels[b * NP + oi];
        } else {
            boxes_out[base * 4 + 0] = 0.0f;
            boxes_out[base * 4 + 1] = 0.0f;
            boxes_out[base * 4 + 2] = 0.0f;
            boxes_out[base * 4 + 3] = 0.0f;
            scores_out[base] = 0.0f;
            labels_out[base] = -1.0f;
        }
    }
}

// ---------------- launch ----------------
extern "C" void kernel_launch(void* const* d_in, const int* in_sizes, int n_in,
                              void* d_out, int out_size) {
    const float* class_logits  = (const float*)d_in[0];
    const float* bbox_deltas   = (const float*)d_in[1];
    const float* roi_proposals = (const float*)d_in[2];
    const int*   image_sizes   = (const int*)d_in[3];
    float* out = (float*)d_out;

    int total_warps = NB * NP;
    int threads = 256;
    int blocks = (total_warps * 32 + threads - 1) / threads;
    score_decode_kernel<<<blocks, threads>>>(class_logits, bbox_deltas,
                                             roi_proposals, image_sizes);

    maxcoord_kernel<<<1, 512>>>();

    int nmsW = NB * 90;
    int nmsB = (nmsW + NMS_WARPS_PER_CTA - 1) / NMS_WARPS_PER_CTA;
    nms_class_kernel<<<nmsB, NMS_WARPS_PER_CTA * 32>>>();

    topk_kernel<<<NB, 1024>>>(out);
}